// round 8
// baseline (speedup 1.0000x reference)
#include <cuda_runtime.h>
#include <cuda_fp16.h>
#include <cstdint>

// ---------------------------------------------------------------------------
// LSTM cell, sm_103 base target. R8: fp16 m16n8k16 MMA with FP16 accumulators
// (possible 2x HMMA rate vs f32-acc on the fallback path). Accumulation split
// into two K=1024 chains per output to bound fp16 rounding error; chains are
// fused in fp32 in the epilogue. Otherwise identical to R6 (8 warps, Mw64 x
// Nw48, prepass-converted half operands, 4-stage cp.async pipeline).
// ---------------------------------------------------------------------------

static constexpr int BATCH = 16384;
static constexpr int HID   = 1024;
static constexpr int KTOT  = 2048;
static constexpr int BM    = 128;
static constexpr int BN_G  = 64;
static constexpr int GATES = 3;
static constexpr int BK    = 64;           // halfs per stage row (128B)
static constexpr int KSTEPS = KTOT / BK;   // 32
static constexpr int NSTAGE = 4;
static constexpr int NTHR   = 256;

static constexpr uint32_t A_ST  = BM * 128;            // 16 KB
static constexpr uint32_t B_ST  = GATES * BN_G * 128;  // 24 KB
static constexpr uint32_t STAGE = A_ST + B_ST;         // 40 KB
static constexpr uint32_t SMEM_BYTES = NSTAGE * STAGE + 1024;

__device__ __half g_X[(long)BATCH * KTOT];
__device__ __half g_W[(long)GATES * HID * KTOT];

__device__ __forceinline__ uint32_t smem_u32(const void* p) {
    uint32_t a;
    asm("{ .reg .u64 t; cvta.to.shared.u64 t, %1; cvt.u32.u64 %0, t; }"
        : "=r"(a) : "l"(p));
    return a;
}

#define CP_ASYNC16(dst, src) \
    asm volatile("cp.async.cg.shared.global [%0], [%1], 16;" :: "r"(dst), "l"(src) : "memory")
#define CP_COMMIT() asm volatile("cp.async.commit_group;" ::: "memory")

#define LDSM4(r, addr)                                                         \
    asm volatile("ldmatrix.sync.aligned.m8n8.x4.shared.b16 {%0,%1,%2,%3}, [%4];" \
        : "=r"((r)[0]), "=r"((r)[1]), "=r"((r)[2]), "=r"((r)[3]) : "r"(addr))

// fp16-accumulate MMA: D (2x .f16x2 regs) += A*B
#define MMA_F16ACC(d, a, b0, b1)                                               \
    asm volatile("mma.sync.aligned.m16n8k16.row.col.f16.f16.f16.f16 "          \
        "{%0,%1},{%2,%3,%4,%5},{%6,%7},{%0,%1};"                               \
        : "+r"((d)[0]), "+r"((d)[1])                                           \
        : "r"((a)[0]), "r"((a)[1]), "r"((a)[2]), "r"((a)[3]), "r"(b0), "r"(b1))

// ---- prepass ---------------------------------------------------------------
__global__ __launch_bounds__(256)
void prep_x_kernel(const float* __restrict__ x, const float* __restrict__ h) {
    const long i = (long)blockIdx.x * 256 + threadIdx.x;
    const long row = i >> 8;
    const int  c8  = (int)(i & 255);
    const float4* src = (c8 < 128) ? (const float4*)(x + row * 1024 + c8 * 8)
                                   : (const float4*)(h + row * 1024 + (c8 - 128) * 8);
    const float4 v0 = src[0], v1 = src[1];
    __half2 o[4];
    o[0] = __floats2half2_rn(v0.x, v0.y);
    o[1] = __floats2half2_rn(v0.z, v0.w);
    o[2] = __floats2half2_rn(v1.x, v1.y);
    o[3] = __floats2half2_rn(v1.z, v1.w);
    ((uint4*)g_X)[i] = *(const uint4*)o;
}

__global__ __launch_bounds__(256)
void prep_w_kernel(const float* __restrict__ Wii, const float* __restrict__ Whi,
                   const float* __restrict__ Wif, const float* __restrict__ Whf,
                   const float* __restrict__ Wig, const float* __restrict__ Whg) {
    const long i = (long)blockIdx.x * 256 + threadIdx.x;
    const long grow = i >> 8;
    const int  c8   = (int)(i & 255);
    const int  g    = (int)(grow >> 10);
    const long r    = grow & 1023;
    const float* Wx = (g == 0) ? Wii : (g == 1) ? Wif : Wig;
    const float* Wh = (g == 0) ? Whi : (g == 1) ? Whf : Whg;
    const float4* src = (c8 < 128) ? (const float4*)(Wx + r * 1024 + c8 * 8)
                                   : (const float4*)(Wh + r * 1024 + (c8 - 128) * 8);
    const float4 v0 = src[0], v1 = src[1];
    __half2 o[4];
    o[0] = __floats2half2_rn(v0.x, v0.y);
    o[1] = __floats2half2_rn(v0.z, v0.w);
    o[2] = __floats2half2_rn(v1.x, v1.y);
    o[3] = __floats2half2_rn(v1.z, v1.w);
    ((uint4*)g_W)[i] = *(const uint4*)o;
}

__device__ __forceinline__ float lstm_elem(float gi, float gf, float gg,
                                           float bi, float bf, float bg, float cv) {
    float vi = gi + bi;
    float vf = gf + bf;
    float vg = gg + bg;
    float si = 1.0f / (1.0f + __expf(-vi));
    float sf = 1.0f / (1.0f + __expf(-vf));
    float vgc = fminf(15.0f, fmaxf(-15.0f, vg));
    float e2  = __expf(2.0f * vgc);
    float tg  = (e2 - 1.0f) / (e2 + 1.0f);
    return fmaf(sf, cv, si * tg);
}

__global__ __launch_bounds__(NTHR, 1)
void lstm_mma_kernel(const float* __restrict__ c,
                     const float* __restrict__ bii, const float* __restrict__ bhi,
                     const float* __restrict__ bif, const float* __restrict__ bhf,
                     const float* __restrict__ big, const float* __restrict__ bhg,
                     float* __restrict__ out) {
    extern __shared__ char smem_raw[];
    const uint32_t raw   = smem_u32(smem_raw);
    const uint32_t tiles = (raw + 1023u) & ~1023u;
    float* bias = (float*)(smem_raw + (tiles - raw) + NSTAGE * STAGE);

    const int tid  = threadIdx.x;
    const int lane = tid & 31;
    const int wid  = tid >> 5;
    const int wm   = wid >> 2;
    const int wn   = wid & 3;

    const int m0 = (int)(blockIdx.x >> 4) * BM;
    const int n0 = (int)(blockIdx.x & 15) * BN_G;

    if (tid < 192) {
        const int g = tid >> 6, j = tid & 63, n = n0 + j;
        float v;
        if (g == 0)      v = bii[n] + bhi[n];
        else if (g == 1) v = bif[n] + bhf[n];
        else             v = big[n] + bhg[n];
        bias[tid] = v;
    }

    // producer invariants ----------------------------------------------------
    uint32_t aoffs[4]; const __half* asrc[4];
    #pragma unroll
    for (int i = 0; i < 4; ++i) {
        const int id = tid + i * NTHR;
        const int row = id >> 3, ch = id & 7;
        aoffs[i] = (uint32_t)(row * 128 + ((ch ^ (row & 7)) << 4));
        asrc[i]  = g_X + (long)(m0 + row) * KTOT + ch * 8;
    }
    uint32_t boffs[6]; const __half* bsrc[6];
    #pragma unroll
    for (int i = 0; i < 6; ++i) {
        const int id = tid + i * NTHR;
        const int grow = id >> 3, ch = id & 7;
        const int g = grow >> 6, r = grow & 63;
        boffs[i] = (uint32_t)(grow * 128 + ((ch ^ (r & 7)) << 4));
        bsrc[i]  = g_W + (long)(g * HID + n0 + r) * KTOT + ch * 8;
    }

    // consumer invariants ----------------------------------------------------
    const int a_r  = (lane & 7) + ((lane >> 3) & 1) * 8;
    const int a_kx = lane >> 4;
    const int b_r  = (lane & 7) + ((lane >> 4) << 3);
    const int b_kx = (lane >> 3) & 1;

    uint32_t arow[4], brow[GATES];
    #pragma unroll
    for (int mt = 0; mt < 4; ++mt)
        arow[mt] = (uint32_t)((wm * 64 + mt * 16 + a_r) * 128);
    #pragma unroll
    for (int g = 0; g < GATES; ++g)
        brow[g] = (uint32_t)((g * 64 + wn * 16 + b_r) * 128);

    const uint32_t a_s7 = (uint32_t)(a_r & 7);
    const uint32_t b_s7 = (uint32_t)(b_r & 7);

    // fp16 accumulators, two K-chains [ch][g][mt][nt][rh-reg]
    uint32_t hacc[2][GATES][4][2][2];
    #pragma unroll
    for (int ch = 0; ch < 2; ++ch)
        #pragma unroll
        for (int g = 0; g < GATES; ++g)
            #pragma unroll
            for (int mt = 0; mt < 4; ++mt)
                #pragma unroll
                for (int nt = 0; nt < 2; ++nt) {
                    hacc[ch][g][mt][nt][0] = 0u;
                    hacc[ch][g][mt][nt][1] = 0u;
                }

    auto load_stage = [&](int s, int ks) {
        const int kk = ks * BK;
        const uint32_t sAs = tiles + (uint32_t)s * STAGE;
        const uint32_t sBs = sAs + A_ST;
        #pragma unroll
        for (int i = 0; i < 4; ++i)
            CP_ASYNC16(sAs + aoffs[i], asrc[i] + kk);
        #pragma unroll
        for (int i = 0; i < 6; ++i)
            CP_ASYNC16(sBs + boffs[i], bsrc[i] + kk);
    };

    #pragma unroll
    for (int s = 0; s < NSTAGE - 1; ++s) { load_stage(s, s); CP_COMMIT(); }

    #pragma unroll 1
    for (int half = 0; half < 2; ++half) {
        #pragma unroll 1
        for (int kh = 0; kh < KSTEPS / 2; ++kh) {
            const int ks = half * (KSTEPS / 2) + kh;
            asm volatile("cp.async.wait_group %0;" :: "n"(NSTAGE - 2));
            __syncthreads();

            const uint32_t sAs = tiles + (uint32_t)(ks & (NSTAGE - 1)) * STAGE;
            const uint32_t sBs = sAs + A_ST;

            #pragma unroll
            for (int kst = 0; kst < 4; ++kst) {
                const uint32_t aoff = (uint32_t)(((kst * 2 + a_kx) ^ a_s7) << 4);
                const uint32_t boff = (uint32_t)(((kst * 2 + b_kx) ^ b_s7) << 4);
                uint32_t a[4][4], b[GATES][4];
                #pragma unroll
                for (int mt = 0; mt < 4; ++mt) LDSM4(a[mt], sAs + arow[mt] + aoff);
                #pragma unroll
                for (int g = 0; g < GATES; ++g) LDSM4(b[g], sBs + brow[g] + boff);
                #pragma unroll
                for (int g = 0; g < GATES; ++g)
                    #pragma unroll
                    for (int mt = 0; mt < 4; ++mt) {
                        MMA_F16ACC(hacc[half][g][mt][0], a[mt], b[g][0], b[g][1]);
                        MMA_F16ACC(hacc[half][g][mt][1], a[mt], b[g][2], b[g][3]);
                    }
            }

            const int pf = ks + NSTAGE - 1;
            if (pf < KSTEPS) load_stage(pf & (NSTAGE - 1), pf);
            CP_COMMIT();
        }
    }

    // epilogue: fuse the two fp16 chains in fp32, then LSTM ------------------
    #pragma unroll
    for (int mt = 0; mt < 4; ++mt) {
        const int mrow = m0 + wm * 64 + mt * 16 + (lane >> 2);
        #pragma unroll
        for (int nt = 0; nt < 2; ++nt) {
            const int nl = wn * 16 + nt * 8 + (lane & 3) * 2;
            const float bi0 = bias[nl],       bi1 = bias[nl + 1];
            const float bf0 = bias[64 + nl],  bf1 = bias[64 + nl + 1];
            const float bg0 = bias[128 + nl], bg1 = bias[128 + nl + 1];
            #pragma unroll
            for (int rh = 0; rh < 2; ++rh) {
                float2 gv[GATES];
                #pragma unroll
                for (int g = 0; g < GATES; ++g) {
                    const __half2 h0 = *(__half2*)&hacc[0][g][mt][nt][rh];
                    const __half2 h1 = *(__half2*)&hacc[1][g][mt][nt][rh];
                    const float2 f0 = __half22float2(h0);
                    const float2 f1 = __half22float2(h1);
                    gv[g] = make_float2(f0.x + f1.x, f0.y + f1.y);
                }
                const long idx = (long)(mrow + rh * 8) * HID + n0 + nl;
                const float2 cv = *(const float2*)(c + idx);
                float2 ov;
                ov.x = lstm_elem(gv[0].x, gv[1].x, gv[2].x, bi0, bf0, bg0, cv.x);
                ov.y = lstm_elem(gv[0].y, gv[1].y, gv[2].y, bi1, bf1, bg1, cv.y);
                *(float2*)(out + idx) = ov;
            }
        }
    }
}

extern "C" void kernel_launch(void* const* d_in, const int* in_sizes, int n_in,
                              void* d_out, int out_size) {
    const float* x   = (const float*)d_in[0];
    const float* h   = (const float*)d_in[1];
    const float* c   = (const float*)d_in[2];
    const float* Wii = (const float*)d_in[3];
    const float* bii = (const float*)d_in[4];
    const float* Whi = (const float*)d_in[5];
    const float* bhi = (const float*)d_in[6];
    const float* Wif = (const float*)d_in[7];
    const float* bif = (const float*)d_in[8];
    const float* Whf = (const float*)d_in[9];
    const float* bhf = (const float*)d_in[10];
    const float* Wig = (const float*)d_in[11];
    const float* big = (const float*)d_in[12];
    const float* Whg = (const float*)d_in[13];
    const float* bhg = (const float*)d_in[14];
    float* out = (float*)d_out;

    cudaFuncSetAttribute(lstm_mma_kernel,
                         cudaFuncAttributeMaxDynamicSharedMemorySize, SMEM_BYTES);

    prep_x_kernel<<<(long)BATCH * KTOT / 8 / 256, 256>>>(x, h);
    prep_w_kernel<<<(long)GATES * HID * KTOT / 8 / 256, 256>>>(
        Wii, Whi, Wif, Whf, Wig, Whg);

    dim3 grid((BATCH / BM) * (HID / BN_G));
    lstm_mma_kernel<<<grid, NTHR, SMEM_BYTES>>>(
        c, bii, bhi, bif, bhf, big, bhg, out);
}

// round 10
// speedup vs baseline: 1.5086x; 1.5086x over previous
#include <cuda_runtime.h>
#include <cuda_fp16.h>
#include <cstdint>

// ---------------------------------------------------------------------------
// LSTM cell, sm_103 base target. R10: R6 champion mainloop (fp16 m16n8k16,
// f32 accumulators, 8 warps, Mw64 x Nw48) + merged prep kernel with FIXED
// W-chunk indexing (256 chunks per 2048-col row; R9 used 128 — garbage).
// ---------------------------------------------------------------------------

static constexpr int BATCH = 16384;
static constexpr int HID   = 1024;
static constexpr int KTOT  = 2048;
static constexpr int BM    = 128;
static constexpr int BN_G  = 64;
static constexpr int GATES = 3;
static constexpr int BK    = 64;           // halfs per stage row (128B)
static constexpr int KSTEPS = KTOT / BK;   // 32
static constexpr int NSTAGE = 4;
static constexpr int NTHR   = 256;

static constexpr uint32_t A_ST  = BM * 128;            // 16 KB
static constexpr uint32_t B_ST  = GATES * BN_G * 128;  // 24 KB
static constexpr uint32_t STAGE = A_ST + B_ST;         // 40 KB
static constexpr uint32_t SMEM_BYTES = NSTAGE * STAGE + 1024;

// prep geometry: each thread converts 8 f32 -> 8 half (one 16B store)
static constexpr long XCHUNKS = (long)BATCH * KTOT / 8;           // 4,194,304
static constexpr long WCHUNKS = (long)GATES * HID * KTOT / 8;     // 786,432
static constexpr int  PREP_THR = 512;
static constexpr long PREP_BLOCKS = (XCHUNKS + WCHUNKS + PREP_THR - 1) / PREP_THR;

__device__ __half g_X[(long)BATCH * KTOT];          // 67 MB
__device__ __half g_W[(long)GATES * HID * KTOT];    // 12.6 MB

__device__ __forceinline__ uint32_t smem_u32(const void* p) {
    uint32_t a;
    asm("{ .reg .u64 t; cvta.to.shared.u64 t, %1; cvt.u32.u64 %0, t; }"
        : "=r"(a) : "l"(p));
    return a;
}

#define CP_ASYNC16(dst, src) \
    asm volatile("cp.async.cg.shared.global [%0], [%1], 16;" :: "r"(dst), "l"(src) : "memory")
#define CP_COMMIT() asm volatile("cp.async.commit_group;" ::: "memory")

#define LDSM4(r, addr)                                                         \
    asm volatile("ldmatrix.sync.aligned.m8n8.x4.shared.b16 {%0,%1,%2,%3}, [%4];" \
        : "=r"((r)[0]), "=r"((r)[1]), "=r"((r)[2]), "=r"((r)[3]) : "r"(addr))

#define MMA_F16(d, a, b0, b1)                                                  \
    asm volatile("mma.sync.aligned.m16n8k16.row.col.f32.f16.f16.f32 "          \
        "{%0,%1,%2,%3},{%4,%5,%6,%7},{%8,%9},{%0,%1,%2,%3};"                   \
        : "+f"((d)[0]), "+f"((d)[1]), "+f"((d)[2]), "+f"((d)[3])               \
        : "r"((a)[0]), "r"((a)[1]), "r"((a)[2]), "r"((a)[3]), "r"(b0), "r"(b1))

__device__ __forceinline__ void cvt_store8(const float4* __restrict__ src,
                                           uint4* __restrict__ dst) {
    const float4 v0 = src[0], v1 = src[1];
    __half2 o[4];
    o[0] = __floats2half2_rn(v0.x, v0.y);
    o[1] = __floats2half2_rn(v0.z, v0.w);
    o[2] = __floats2half2_rn(v1.x, v1.y);
    o[3] = __floats2half2_rn(v1.z, v1.w);
    *dst = *(const uint4*)o;
}

// ---- merged prepass: [x|h] -> g_X  and gate-concat W -> g_W ---------------
// Both g_X and g_W rows are KTOT = 2048 halfs = 256 chunks of 8.
__global__ __launch_bounds__(PREP_THR)
void prep_kernel(const float* __restrict__ x,   const float* __restrict__ h,
                 const float* __restrict__ Wii, const float* __restrict__ Whi,
                 const float* __restrict__ Wif, const float* __restrict__ Whf,
                 const float* __restrict__ Wig, const float* __restrict__ Whg) {
    const long i = (long)blockIdx.x * PREP_THR + threadIdx.x;
    if (i < XCHUNKS) {
        const long row = i >> 8;               // 256 chunks per row
        const int  c8  = (int)(i & 255);
        const float4* src = (c8 < 128)
            ? (const float4*)(x + row * 1024 + c8 * 8)
            : (const float4*)(h + row * 1024 + (c8 - 128) * 8);
        cvt_store8(src, (uint4*)g_X + i);
    } else if (i < XCHUNKS + WCHUNKS) {
        const long j = i - XCHUNKS;
        const long grow = j >> 8;              // 256 chunks per row (FIXED)
        const int  c8   = (int)(j & 255);
        const int  g    = (int)(grow >> 10);   // 0..2
        const long r    = grow & 1023;
        const float* Wx = (g == 0) ? Wii : (g == 1) ? Wif : Wig;
        const float* Wh = (g == 0) ? Whi : (g == 1) ? Whf : Whg;
        const float4* src = (c8 < 128)
            ? (const float4*)(Wx + r * 1024 + c8 * 8)
            : (const float4*)(Wh + r * 1024 + (c8 - 128) * 8);
        cvt_store8(src, (uint4*)g_W + j);
    }
}

__device__ __forceinline__ float lstm_elem(float gi, float gf, float gg,
                                           float bi, float bf, float bg, float cv) {
    float vi = gi + bi;
    float vf = gf + bf;
    float vg = gg + bg;
    float si = 1.0f / (1.0f + __expf(-vi));
    float sf = 1.0f / (1.0f + __expf(-vf));
    float vgc = fminf(15.0f, fmaxf(-15.0f, vg));
    float e2  = __expf(2.0f * vgc);
    float tg  = (e2 - 1.0f) / (e2 + 1.0f);
    return fmaf(sf, cv, si * tg);
}

__global__ __launch_bounds__(NTHR, 1)
void lstm_mma_kernel(const float* __restrict__ c,
                     const float* __restrict__ bii, const float* __restrict__ bhi,
                     const float* __restrict__ bif, const float* __restrict__ bhf,
                     const float* __restrict__ big, const float* __restrict__ bhg,
                     float* __restrict__ out) {
    extern __shared__ char smem_raw[];
    const uint32_t raw   = smem_u32(smem_raw);
    const uint32_t tiles = (raw + 1023u) & ~1023u;
    float* bias = (float*)(smem_raw + (tiles - raw) + NSTAGE * STAGE);

    const int tid  = threadIdx.x;
    const int lane = tid & 31;
    const int wid  = tid >> 5;
    const int wm   = wid >> 2;
    const int wn   = wid & 3;

    const int m0 = (int)(blockIdx.x >> 4) * BM;
    const int n0 = (int)(blockIdx.x & 15) * BN_G;

    if (tid < 192) {
        const int g = tid >> 6, j = tid & 63, n = n0 + j;
        float v;
        if (g == 0)      v = bii[n] + bhi[n];
        else if (g == 1) v = bif[n] + bhf[n];
        else             v = big[n] + bhg[n];
        bias[tid] = v;
    }

    // producer invariants ----------------------------------------------------
    uint32_t aoffs[4]; const __half* asrc[4];
    #pragma unroll
    for (int i = 0; i < 4; ++i) {
        const int id = tid + i * NTHR;
        const int row = id >> 3, ch = id & 7;
        aoffs[i] = (uint32_t)(row * 128 + ((ch ^ (row & 7)) << 4));
        asrc[i]  = g_X + (long)(m0 + row) * KTOT + ch * 8;
    }
    uint32_t boffs[6]; const __half* bsrc[6];
    #pragma unroll
    for (int i = 0; i < 6; ++i) {
        const int id = tid + i * NTHR;
        const int grow = id >> 3, ch = id & 7;
        const int g = grow >> 6, r = grow & 63;
        boffs[i] = (uint32_t)(grow * 128 + ((ch ^ (r & 7)) << 4));
        bsrc[i]  = g_W + (long)(g * HID + n0 + r) * KTOT + ch * 8;
    }

    // consumer invariants ----------------------------------------------------
    const int a_r  = (lane & 7) + ((lane >> 3) & 1) * 8;
    const int a_kx = lane >> 4;
    const int b_r  = (lane & 7) + ((lane >> 4) << 3);
    const int b_kx = (lane >> 3) & 1;

    uint32_t arow[4], brow[GATES];
    #pragma unroll
    for (int mt = 0; mt < 4; ++mt)
        arow[mt] = (uint32_t)((wm * 64 + mt * 16 + a_r) * 128);
    #pragma unroll
    for (int g = 0; g < GATES; ++g)
        brow[g] = (uint32_t)((g * 64 + wn * 16 + b_r) * 128);

    const uint32_t a_s7 = (uint32_t)(a_r & 7);
    const uint32_t b_s7 = (uint32_t)(b_r & 7);

    float acc[GATES][4][2][4];
    #pragma unroll
    for (int g = 0; g < GATES; ++g)
        #pragma unroll
        for (int mt = 0; mt < 4; ++mt)
            #pragma unroll
            for (int nt = 0; nt < 2; ++nt)
                #pragma unroll
                for (int q = 0; q < 4; ++q) acc[g][mt][nt][q] = 0.0f;

    auto load_stage = [&](int s, int ks) {
        const int kk = ks * BK;
        const uint32_t sAs = tiles + (uint32_t)s * STAGE;
        const uint32_t sBs = sAs + A_ST;
        #pragma unroll
        for (int i = 0; i < 4; ++i)
            CP_ASYNC16(sAs + aoffs[i], asrc[i] + kk);
        #pragma unroll
        for (int i = 0; i < 6; ++i)
            CP_ASYNC16(sBs + boffs[i], bsrc[i] + kk);
    };

    #pragma unroll
    for (int s = 0; s < NSTAGE - 1; ++s) { load_stage(s, s); CP_COMMIT(); }

    for (int ks = 0; ks < KSTEPS; ++ks) {
        asm volatile("cp.async.wait_group %0;" :: "n"(NSTAGE - 2));
        __syncthreads();

        const uint32_t sAs = tiles + (uint32_t)(ks & (NSTAGE - 1)) * STAGE;
        const uint32_t sBs = sAs + A_ST;

        #pragma unroll
        for (int kst = 0; kst < 4; ++kst) {
            const uint32_t aoff = (uint32_t)(((kst * 2 + a_kx) ^ a_s7) << 4);
            const uint32_t boff = (uint32_t)(((kst * 2 + b_kx) ^ b_s7) << 4);
            uint32_t a[4][4], b[GATES][4];
            #pragma unroll
            for (int mt = 0; mt < 4; ++mt) LDSM4(a[mt], sAs + arow[mt] + aoff);
            #pragma unroll
            for (int g = 0; g < GATES; ++g) LDSM4(b[g], sBs + brow[g] + boff);
            #pragma unroll
            for (int g = 0; g < GATES; ++g)
                #pragma unroll
                for (int mt = 0; mt < 4; ++mt) {
                    MMA_F16(acc[g][mt][0], a[mt], b[g][0], b[g][1]);
                    MMA_F16(acc[g][mt][1], a[mt], b[g][2], b[g][3]);
                }
        }

        const int pf = ks + NSTAGE - 1;
        if (pf < KSTEPS) load_stage(pf & (NSTAGE - 1), pf);
        CP_COMMIT();
    }

    // epilogue: register-resident --------------------------------------------
    #pragma unroll
    for (int mt = 0; mt < 4; ++mt) {
        const int mrow = m0 + wm * 64 + mt * 16 + (lane >> 2);
        #pragma unroll
        for (int nt = 0; nt < 2; ++nt) {
            const int nl = wn * 16 + nt * 8 + (lane & 3) * 2;
            const float bi0 = bias[nl],       bi1 = bias[nl + 1];
            const float bf0 = bias[64 + nl],  bf1 = bias[64 + nl + 1];
            const float bg0 = bias[128 + nl], bg1 = bias[128 + nl + 1];
            #pragma unroll
            for (int rh = 0; rh < 2; ++rh) {
                const long idx = (long)(mrow + rh * 8) * HID + n0 + nl;
                const float2 cv = *(const float2*)(c + idx);
                float2 ov;
                ov.x = lstm_elem(acc[0][mt][nt][rh * 2],
                                 acc[1][mt][nt][rh * 2],
                                 acc[2][mt][nt][rh * 2], bi0, bf0, bg0, cv.x);
                ov.y = lstm_elem(acc[0][mt][nt][rh * 2 + 1],
                                 acc[1][mt][nt][rh * 2 + 1],
                                 acc[2][mt][nt][rh * 2 + 1], bi1, bf1, bg1, cv.y);
                *(float2*)(out + idx) = ov;
            }
        }
    }
}

extern "C" void kernel_launch(void* const* d_in, const int* in_sizes, int n_in,
                              void* d_out, int out_size) {
    const float* x   = (const float*)d_in[0];
    const float* h   = (const float*)d_in[1];
    const float* c   = (const float*)d_in[2];
    const float* Wii = (const float*)d_in[3];
    const float* bii = (const float*)d_in[4];
    const float* Whi = (const float*)d_in[5];
    const float* bhi = (const float*)d_in[6];
    const float* Wif = (const float*)d_in[7];
    const float* bif = (const float*)d_in[8];
    const float* Whf = (const float*)d_in[9];
    const float* bhf = (const float*)d_in[10];
    const float* Wig = (const float*)d_in[11];
    const float* big = (const float*)d_in[12];
    const float* Whg = (const float*)d_in[13];
    const float* bhg = (const float*)d_in[14];
    float* out = (float*)d_out;

    cudaFuncSetAttribute(lstm_mma_kernel,
                         cudaFuncAttributeMaxDynamicSharedMemorySize, SMEM_BYTES);

    prep_kernel<<<(int)PREP_BLOCKS, PREP_THR>>>(x, h, Wii, Whi, Wif, Whf, Wig, Whg);

    dim3 grid((BATCH / BM) * (HID / BN_G));
    lstm_mma_kernel<<<grid, NTHR, SMEM_BYTES>>>(
        c, bii, bhi, bif, bhf, big, bhg, out);
}

// round 11
// speedup vs baseline: 1.5443x; 1.0237x over previous
#include <cuda_runtime.h>
#include <cuda_fp16.h>
#include <cstdint>

// ---------------------------------------------------------------------------
// LSTM cell, sm_103 base target. R11: fp16 m16n8k16 mainloop at 512 threads /
// 16 warps (4 warps/SMSP). ncu showed tensor pipe only 56.5% busy with 2
// warps/SMSP contributing ~28% each, near-additive -> 4 warps/SMSP should
// saturate the pipe. Warp tile Mw32 x 16 cols/gate (R4 geometry), acc=48 f32.
// Merged f32->half prep kernel (R10).
// ---------------------------------------------------------------------------

static constexpr int BATCH = 16384;
static constexpr int HID   = 1024;
static constexpr int KTOT  = 2048;
static constexpr int BM    = 128;
static constexpr int BN_G  = 64;
static constexpr int GATES = 3;
static constexpr int BK    = 64;           // halfs per stage row (128B)
static constexpr int KSTEPS = KTOT / BK;   // 32
static constexpr int NSTAGE = 4;
static constexpr int NTHR   = 512;

static constexpr uint32_t A_ST  = BM * 128;            // 16 KB
static constexpr uint32_t B_ST  = GATES * BN_G * 128;  // 24 KB
static constexpr uint32_t STAGE = A_ST + B_ST;         // 40 KB
static constexpr uint32_t SMEM_BYTES = NSTAGE * STAGE + 1024;

static constexpr long XCHUNKS = (long)BATCH * KTOT / 8;
static constexpr long WCHUNKS = (long)GATES * HID * KTOT / 8;
static constexpr int  PREP_THR = 512;
static constexpr long PREP_BLOCKS = (XCHUNKS + WCHUNKS + PREP_THR - 1) / PREP_THR;

__device__ __half g_X[(long)BATCH * KTOT];
__device__ __half g_W[(long)GATES * HID * KTOT];

__device__ __forceinline__ uint32_t smem_u32(const void* p) {
    uint32_t a;
    asm("{ .reg .u64 t; cvta.to.shared.u64 t, %1; cvt.u32.u64 %0, t; }"
        : "=r"(a) : "l"(p));
    return a;
}

#define CP_ASYNC16(dst, src) \
    asm volatile("cp.async.cg.shared.global [%0], [%1], 16;" :: "r"(dst), "l"(src) : "memory")
#define CP_COMMIT() asm volatile("cp.async.commit_group;" ::: "memory")

#define LDSM4(r, addr)                                                         \
    asm volatile("ldmatrix.sync.aligned.m8n8.x4.shared.b16 {%0,%1,%2,%3}, [%4];" \
        : "=r"((r)[0]), "=r"((r)[1]), "=r"((r)[2]), "=r"((r)[3]) : "r"(addr))

#define MMA_F16(d, a, b0, b1)                                                  \
    asm volatile("mma.sync.aligned.m16n8k16.row.col.f32.f16.f16.f32 "          \
        "{%0,%1,%2,%3},{%4,%5,%6,%7},{%8,%9},{%0,%1,%2,%3};"                   \
        : "+f"((d)[0]), "+f"((d)[1]), "+f"((d)[2]), "+f"((d)[3])               \
        : "r"((a)[0]), "r"((a)[1]), "r"((a)[2]), "r"((a)[3]), "r"(b0), "r"(b1))

__device__ __forceinline__ void cvt_store8(const float4* __restrict__ src,
                                           uint4* __restrict__ dst) {
    const float4 v0 = src[0], v1 = src[1];
    __half2 o[4];
    o[0] = __floats2half2_rn(v0.x, v0.y);
    o[1] = __floats2half2_rn(v0.z, v0.w);
    o[2] = __floats2half2_rn(v1.x, v1.y);
    o[3] = __floats2half2_rn(v1.z, v1.w);
    *dst = *(const uint4*)o;
}

__global__ __launch_bounds__(PREP_THR)
void prep_kernel(const float* __restrict__ x,   const float* __restrict__ h,
                 const float* __restrict__ Wii, const float* __restrict__ Whi,
                 const float* __restrict__ Wif, const float* __restrict__ Whf,
                 const float* __restrict__ Wig, const float* __restrict__ Whg) {
    const long i = (long)blockIdx.x * PREP_THR + threadIdx.x;
    if (i < XCHUNKS) {
        const long row = i >> 8;
        const int  c8  = (int)(i & 255);
        const float4* src = (c8 < 128)
            ? (const float4*)(x + row * 1024 + c8 * 8)
            : (const float4*)(h + row * 1024 + (c8 - 128) * 8);
        cvt_store8(src, (uint4*)g_X + i);
    } else if (i < XCHUNKS + WCHUNKS) {
        const long j = i - XCHUNKS;
        const long grow = j >> 8;
        const int  c8   = (int)(j & 255);
        const int  g    = (int)(grow >> 10);
        const long r    = grow & 1023;
        const float* Wx = (g == 0) ? Wii : (g == 1) ? Wif : Wig;
        const float* Wh = (g == 0) ? Whi : (g == 1) ? Whf : Whg;
        const float4* src = (c8 < 128)
            ? (const float4*)(Wx + r * 1024 + c8 * 8)
            : (const float4*)(Wh + r * 1024 + (c8 - 128) * 8);
        cvt_store8(src, (uint4*)g_W + j);
    }
}

__device__ __forceinline__ float lstm_elem(float gi, float gf, float gg,
                                           float bi, float bf, float bg, float cv) {
    float vi = gi + bi;
    float vf = gf + bf;
    float vg = gg + bg;
    float si = 1.0f / (1.0f + __expf(-vi));
    float sf = 1.0f / (1.0f + __expf(-vf));
    float vgc = fminf(15.0f, fmaxf(-15.0f, vg));
    float e2  = __expf(2.0f * vgc);
    float tg  = (e2 - 1.0f) / (e2 + 1.0f);
    return fmaf(sf, cv, si * tg);
}

__global__ __launch_bounds__(NTHR, 1)
void lstm_mma_kernel(const float* __restrict__ c,
                     const float* __restrict__ bii, const float* __restrict__ bhi,
                     const float* __restrict__ bif, const float* __restrict__ bhf,
                     const float* __restrict__ big, const float* __restrict__ bhg,
                     float* __restrict__ out) {
    extern __shared__ char smem_raw[];
    const uint32_t raw   = smem_u32(smem_raw);
    const uint32_t tiles = (raw + 1023u) & ~1023u;
    float* bias = (float*)(smem_raw + (tiles - raw) + NSTAGE * STAGE);

    const int tid  = threadIdx.x;
    const int lane = tid & 31;
    const int wid  = tid >> 5;
    const int wm   = wid >> 2;      // 0..3 : 32-row M tile
    const int wn   = wid & 3;       // 0..3 : 16 cols per gate

    const int m0 = (int)(blockIdx.x >> 4) * BM;
    const int n0 = (int)(blockIdx.x & 15) * BN_G;

    if (tid < 192) {
        const int g = tid >> 6, j = tid & 63, n = n0 + j;
        float v;
        if (g == 0)      v = bii[n] + bhi[n];
        else if (g == 1) v = bif[n] + bhf[n];
        else             v = big[n] + bhg[n];
        bias[tid] = v;
    }

    // producer invariants (512 threads) --------------------------------------
    uint32_t aoffs[2]; const __half* asrc[2];
    #pragma unroll
    for (int i = 0; i < 2; ++i) {
        const int id = tid + i * NTHR;
        const int row = id >> 3, ch = id & 7;
        aoffs[i] = (uint32_t)(row * 128 + ((ch ^ (row & 7)) << 4));
        asrc[i]  = g_X + (long)(m0 + row) * KTOT + ch * 8;
    }
    uint32_t boffs[3]; const __half* bsrc[3];
    #pragma unroll
    for (int i = 0; i < 3; ++i) {
        const int id = tid + i * NTHR;
        const int grow = id >> 3, ch = id & 7;
        const int g = grow >> 6, r = grow & 63;
        boffs[i] = (uint32_t)(grow * 128 + ((ch ^ (r & 7)) << 4));
        bsrc[i]  = g_W + (long)(g * HID + n0 + r) * KTOT + ch * 8;
    }

    // consumer invariants ----------------------------------------------------
    const int a_r  = (lane & 7) + ((lane >> 3) & 1) * 8;
    const int a_kx = lane >> 4;
    const int b_r  = (lane & 7) + ((lane >> 4) << 3);
    const int b_kx = (lane >> 3) & 1;

    uint32_t arow[2], brow[GATES];
    #pragma unroll
    for (int mt = 0; mt < 2; ++mt)
        arow[mt] = (uint32_t)((wm * 32 + mt * 16 + a_r) * 128);
    #pragma unroll
    for (int g = 0; g < GATES; ++g)
        brow[g] = (uint32_t)((g * 64 + wn * 16 + b_r) * 128);

    const uint32_t a_s7 = (uint32_t)(a_r & 7);
    const uint32_t b_s7 = (uint32_t)(b_r & 7);

    float acc[GATES][2][2][4];
    #pragma unroll
    for (int g = 0; g < GATES; ++g)
        #pragma unroll
        for (int mt = 0; mt < 2; ++mt)
            #pragma unroll
            for (int nt = 0; nt < 2; ++nt)
                #pragma unroll
                for (int q = 0; q < 4; ++q) acc[g][mt][nt][q] = 0.0f;

    auto load_stage = [&](int s, int ks) {
        const int kk = ks * BK;
        const uint32_t sAs = tiles + (uint32_t)s * STAGE;
        const uint32_t sBs = sAs + A_ST;
        #pragma unroll
        for (int i = 0; i < 2; ++i)
            CP_ASYNC16(sAs + aoffs[i], asrc[i] + kk);
        #pragma unroll
        for (int i = 0; i < 3; ++i)
            CP_ASYNC16(sBs + boffs[i], bsrc[i] + kk);
    };

    #pragma unroll
    for (int s = 0; s < NSTAGE - 1; ++s) { load_stage(s, s); CP_COMMIT(); }

    for (int ks = 0; ks < KSTEPS; ++ks) {
        asm volatile("cp.async.wait_group %0;" :: "n"(NSTAGE - 2));
        __syncthreads();

        const uint32_t sAs = tiles + (uint32_t)(ks & (NSTAGE - 1)) * STAGE;
        const uint32_t sBs = sAs + A_ST;

        #pragma unroll
        for (int kst = 0; kst < 4; ++kst) {
            const uint32_t aoff = (uint32_t)(((kst * 2 + a_kx) ^ a_s7) << 4);
            const uint32_t boff = (uint32_t)(((kst * 2 + b_kx) ^ b_s7) << 4);
            uint32_t a[2][4], b[GATES][4];
            #pragma unroll
            for (int mt = 0; mt < 2; ++mt) LDSM4(a[mt], sAs + arow[mt] + aoff);
            #pragma unroll
            for (int g = 0; g < GATES; ++g) LDSM4(b[g], sBs + brow[g] + boff);
            #pragma unroll
            for (int g = 0; g < GATES; ++g)
                #pragma unroll
                for (int mt = 0; mt < 2; ++mt) {
                    MMA_F16(acc[g][mt][0], a[mt], b[g][0], b[g][1]);
                    MMA_F16(acc[g][mt][1], a[mt], b[g][2], b[g][3]);
                }
        }

        const int pf = ks + NSTAGE - 1;
        if (pf < KSTEPS) load_stage(pf & (NSTAGE - 1), pf);
        CP_COMMIT();
    }

    // epilogue: register-resident --------------------------------------------
    #pragma unroll
    for (int mt = 0; mt < 2; ++mt) {
        const int mrow = m0 + wm * 32 + mt * 16 + (lane >> 2);
        #pragma unroll
        for (int nt = 0; nt < 2; ++nt) {
            const int nl = wn * 16 + nt * 8 + (lane & 3) * 2;
            const float bi0 = bias[nl],       bi1 = bias[nl + 1];
            const float bf0 = bias[64 + nl],  bf1 = bias[64 + nl + 1];
            const float bg0 = bias[128 + nl], bg1 = bias[128 + nl + 1];
            #pragma unroll
            for (int rh = 0; rh < 2; ++rh) {
                const long idx = (long)(mrow + rh * 8) * HID + n0 + nl;
                const float2 cv = *(const float2*)(c + idx);
                float2 ov;
                ov.x = lstm_elem(acc[0][mt][nt][rh * 2],
                                 acc[1][mt][nt][rh * 2],
                                 acc[2][mt][nt][rh * 2], bi0, bf0, bg0, cv.x);
                ov.y = lstm_elem(acc[0][mt][nt][rh * 2 + 1],
                                 acc[1][mt][nt][rh * 2 + 1],
                                 acc[2][mt][nt][rh * 2 + 1], bi1, bf1, bg1, cv.y);
                *(float2*)(out + idx) = ov;
            }
        }
    }
}

extern "C" void kernel_launch(void* const* d_in, const int* in_sizes, int n_in,
                              void* d_out, int out_size) {
    const float* x   = (const float*)d_in[0];
    const float* h   = (const float*)d_in[1];
    const float* c   = (const float*)d_in[2];
    const float* Wii = (const float*)d_in[3];
    const float* bii = (const float*)d_in[4];
    const float* Whi = (const float*)d_in[5];
    const float* bhi = (const float*)d_in[6];
    const float* Wif = (const float*)d_in[7];
    const float* bif = (const float*)d_in[8];
    const float* Whf = (const float*)d_in[9];
    const float* bhf = (const float*)d_in[10];
    const float* Wig = (const float*)d_in[11];
    const float* big = (const float*)d_in[12];
    const float* Whg = (const float*)d_in[13];
    const float* bhg = (const float*)d_in[14];
    float* out = (float*)d_out;

    cudaFuncSetAttribute(lstm_mma_kernel,
                         cudaFuncAttributeMaxDynamicSharedMemorySize, SMEM_BYTES);

    prep_kernel<<<(int)PREP_BLOCKS, PREP_THR>>>(x, h, Wii, Whi, Wif, Whf, Wig, Whg);

    dim3 grid((BATCH / BM) * (HID / BN_G));
    lstm_mma_kernel<<<grid, NTHR, SMEM_BYTES>>>(
        c, bii, bhi, bif, bhf, big, bhg, out);
}

// round 12
// speedup vs baseline: 1.8077x; 1.1706x over previous
#include <cuda_runtime.h>
#include <cuda_fp16.h>
#include <cstdint>

// ---------------------------------------------------------------------------
// LSTM cell, sm_103 base target. R12: 2 CTAs/SM to decorrelate per-stage
// __syncthreads drain bubbles (ncu: tensor pinned ~58% with ~1000cyc/stage
// bubble regardless of warps-in-CTA). CTA tile 64 x 192 (BM=64), 256 thr /
// 8 warps (Mw32 x 16 cols/gate), NSTAGE=3 ring (97KB smem) so two CTAs
// co-reside. fp16 m16n8k16, f32 acc. Merged f32->half prep (R10).
// ---------------------------------------------------------------------------

static constexpr int BATCH = 16384;
static constexpr int HID   = 1024;
static constexpr int KTOT  = 2048;
static constexpr int BM    = 64;
static constexpr int BN_G  = 64;
static constexpr int GATES = 3;
static constexpr int BK    = 64;           // halfs per stage row (128B)
static constexpr int KSTEPS = KTOT / BK;   // 32
static constexpr int NSTAGE = 3;
static constexpr int NTHR   = 256;

static constexpr uint32_t A_ST  = BM * 128;            // 8 KB
static constexpr uint32_t B_ST  = GATES * BN_G * 128;  // 24 KB
static constexpr uint32_t STAGE = A_ST + B_ST;         // 32 KB
static constexpr uint32_t SMEM_BYTES = NSTAGE * STAGE + 1024;  // ~97 KB

static constexpr long XCHUNKS = (long)BATCH * KTOT / 8;
static constexpr long WCHUNKS = (long)GATES * HID * KTOT / 8;
static constexpr int  PREP_THR = 512;
static constexpr long PREP_BLOCKS = (XCHUNKS + WCHUNKS + PREP_THR - 1) / PREP_THR;

__device__ __half g_X[(long)BATCH * KTOT];
__device__ __half g_W[(long)GATES * HID * KTOT];

__device__ __forceinline__ uint32_t smem_u32(const void* p) {
    uint32_t a;
    asm("{ .reg .u64 t; cvta.to.shared.u64 t, %1; cvt.u32.u64 %0, t; }"
        : "=r"(a) : "l"(p));
    return a;
}

#define CP_ASYNC16(dst, src) \
    asm volatile("cp.async.cg.shared.global [%0], [%1], 16;" :: "r"(dst), "l"(src) : "memory")
#define CP_COMMIT() asm volatile("cp.async.commit_group;" ::: "memory")

#define LDSM4(r, addr)                                                         \
    asm volatile("ldmatrix.sync.aligned.m8n8.x4.shared.b16 {%0,%1,%2,%3}, [%4];" \
        : "=r"((r)[0]), "=r"((r)[1]), "=r"((r)[2]), "=r"((r)[3]) : "r"(addr))

#define MMA_F16(d, a, b0, b1)                                                  \
    asm volatile("mma.sync.aligned.m16n8k16.row.col.f32.f16.f16.f32 "          \
        "{%0,%1,%2,%3},{%4,%5,%6,%7},{%8,%9},{%0,%1,%2,%3};"                   \
        : "+f"((d)[0]), "+f"((d)[1]), "+f"((d)[2]), "+f"((d)[3])               \
        : "r"((a)[0]), "r"((a)[1]), "r"((a)[2]), "r"((a)[3]), "r"(b0), "r"(b1))

__device__ __forceinline__ void cvt_store8(const float4* __restrict__ src,
                                           uint4* __restrict__ dst) {
    const float4 v0 = src[0], v1 = src[1];
    __half2 o[4];
    o[0] = __floats2half2_rn(v0.x, v0.y);
    o[1] = __floats2half2_rn(v0.z, v0.w);
    o[2] = __floats2half2_rn(v1.x, v1.y);
    o[3] = __floats2half2_rn(v1.z, v1.w);
    *dst = *(const uint4*)o;
}

__global__ __launch_bounds__(PREP_THR)
void prep_kernel(const float* __restrict__ x,   const float* __restrict__ h,
                 const float* __restrict__ Wii, const float* __restrict__ Whi,
                 const float* __restrict__ Wif, const float* __restrict__ Whf,
                 const float* __restrict__ Wig, const float* __restrict__ Whg) {
    const long i = (long)blockIdx.x * PREP_THR + threadIdx.x;
    if (i < XCHUNKS) {
        const long row = i >> 8;
        const int  c8  = (int)(i & 255);
        const float4* src = (c8 < 128)
            ? (const float4*)(x + row * 1024 + c8 * 8)
            : (const float4*)(h + row * 1024 + (c8 - 128) * 8);
        cvt_store8(src, (uint4*)g_X + i);
    } else if (i < XCHUNKS + WCHUNKS) {
        const long j = i - XCHUNKS;
        const long grow = j >> 8;
        const int  c8   = (int)(j & 255);
        const int  g    = (int)(grow >> 10);
        const long r    = grow & 1023;
        const float* Wx = (g == 0) ? Wii : (g == 1) ? Wif : Wig;
        const float* Wh = (g == 0) ? Whi : (g == 1) ? Whf : Whg;
        const float4* src = (c8 < 128)
            ? (const float4*)(Wx + r * 1024 + c8 * 8)
            : (const float4*)(Wh + r * 1024 + (c8 - 128) * 8);
        cvt_store8(src, (uint4*)g_W + j);
    }
}

__device__ __forceinline__ float lstm_elem(float gi, float gf, float gg,
                                           float bi, float bf, float bg, float cv) {
    float vi = gi + bi;
    float vf = gf + bf;
    float vg = gg + bg;
    float si = 1.0f / (1.0f + __expf(-vi));
    float sf = 1.0f / (1.0f + __expf(-vf));
    float vgc = fminf(15.0f, fmaxf(-15.0f, vg));
    float e2  = __expf(2.0f * vgc);
    float tg  = (e2 - 1.0f) / (e2 + 1.0f);
    return fmaf(sf, cv, si * tg);
}

__global__ __launch_bounds__(NTHR, 2)
void lstm_mma_kernel(const float* __restrict__ c,
                     const float* __restrict__ bii, const float* __restrict__ bhi,
                     const float* __restrict__ bif, const float* __restrict__ bhf,
                     const float* __restrict__ big, const float* __restrict__ bhg,
                     float* __restrict__ out) {
    extern __shared__ char smem_raw[];
    const uint32_t raw   = smem_u32(smem_raw);
    const uint32_t tiles = (raw + 1023u) & ~1023u;
    float* bias = (float*)(smem_raw + (tiles - raw) + NSTAGE * STAGE);

    const int tid  = threadIdx.x;
    const int lane = tid & 31;
    const int wid  = tid >> 5;
    const int wm   = wid >> 2;      // 0..1 : 32-row M tile
    const int wn   = wid & 3;       // 0..3 : 16 cols per gate

    const int m0 = (int)(blockIdx.x >> 4) * BM;       // 256 M-tiles
    const int n0 = (int)(blockIdx.x & 15) * BN_G;     // 16 N-blocks

    if (tid < 192) {
        const int g = tid >> 6, j = tid & 63, n = n0 + j;
        float v;
        if (g == 0)      v = bii[n] + bhi[n];
        else if (g == 1) v = bif[n] + bhf[n];
        else             v = big[n] + bhg[n];
        bias[tid] = v;
    }

    // producer invariants: A 512 chunks -> 2/thread, B 1536 chunks -> 6/thread
    uint32_t aoffs[2]; const __half* asrc[2];
    #pragma unroll
    for (int i = 0; i < 2; ++i) {
        const int id = tid + i * NTHR;
        const int row = id >> 3, ch = id & 7;
        aoffs[i] = (uint32_t)(row * 128 + ((ch ^ (row & 7)) << 4));
        asrc[i]  = g_X + (long)(m0 + row) * KTOT + ch * 8;
    }
    uint32_t boffs[6]; const __half* bsrc[6];
    #pragma unroll
    for (int i = 0; i < 6; ++i) {
        const int id = tid + i * NTHR;
        const int grow = id >> 3, ch = id & 7;
        const int g = grow >> 6, r = grow & 63;
        boffs[i] = (uint32_t)(grow * 128 + ((ch ^ (r & 7)) << 4));
        bsrc[i]  = g_W + (long)(g * HID + n0 + r) * KTOT + ch * 8;
    }

    // consumer invariants ----------------------------------------------------
    const int a_r  = (lane & 7) + ((lane >> 3) & 1) * 8;
    const int a_kx = lane >> 4;
    const int b_r  = (lane & 7) + ((lane >> 4) << 3);
    const int b_kx = (lane >> 3) & 1;

    uint32_t arow[2], brow[GATES];
    #pragma unroll
    for (int mt = 0; mt < 2; ++mt)
        arow[mt] = (uint32_t)((wm * 32 + mt * 16 + a_r) * 128);
    #pragma unroll
    for (int g = 0; g < GATES; ++g)
        brow[g] = (uint32_t)((g * 64 + wn * 16 + b_r) * 128);

    const uint32_t a_s7 = (uint32_t)(a_r & 7);
    const uint32_t b_s7 = (uint32_t)(b_r & 7);

    float acc[GATES][2][2][4];
    #pragma unroll
    for (int g = 0; g < GATES; ++g)
        #pragma unroll
        for (int mt = 0; mt < 2; ++mt)
            #pragma unroll
            for (int nt = 0; nt < 2; ++nt)
                #pragma unroll
                for (int q = 0; q < 4; ++q) acc[g][mt][nt][q] = 0.0f;

    auto load_stage = [&](int s, int ks) {
        const int kk = ks * BK;
        const uint32_t sAs = tiles + (uint32_t)s * STAGE;
        const uint32_t sBs = sAs + A_ST;
        #pragma unroll
        for (int i = 0; i < 2; ++i)
            CP_ASYNC16(sAs + aoffs[i], asrc[i] + kk);
        #pragma unroll
        for (int i = 0; i < 6; ++i)
            CP_ASYNC16(sBs + boffs[i], bsrc[i] + kk);
    };

    // prologue: stages 0,1
    #pragma unroll
    for (int s = 0; s < NSTAGE - 1; ++s) { load_stage(s, s); CP_COMMIT(); }

    int sidx = 0;                 // compute-stage ring index
    int pidx = NSTAGE - 1;        // prefetch-stage ring index
    for (int ks = 0; ks < KSTEPS; ++ks) {
        asm volatile("cp.async.wait_group %0;" :: "n"(NSTAGE - 2));
        __syncthreads();

        const uint32_t sAs = tiles + (uint32_t)sidx * STAGE;
        const uint32_t sBs = sAs + A_ST;

        #pragma unroll
        for (int kst = 0; kst < 4; ++kst) {
            const uint32_t aoff = (uint32_t)(((kst * 2 + a_kx) ^ a_s7) << 4);
            const uint32_t boff = (uint32_t)(((kst * 2 + b_kx) ^ b_s7) << 4);
            uint32_t a[2][4], b[GATES][4];
            #pragma unroll
            for (int mt = 0; mt < 2; ++mt) LDSM4(a[mt], sAs + arow[mt] + aoff);
            #pragma unroll
            for (int g = 0; g < GATES; ++g) LDSM4(b[g], sBs + brow[g] + boff);
            #pragma unroll
            for (int g = 0; g < GATES; ++g)
                #pragma unroll
                for (int mt = 0; mt < 2; ++mt) {
                    MMA_F16(acc[g][mt][0], a[mt], b[g][0], b[g][1]);
                    MMA_F16(acc[g][mt][1], a[mt], b[g][2], b[g][3]);
                }
        }

        const int pf = ks + NSTAGE - 1;
        if (pf < KSTEPS) load_stage(pidx, pf);
        CP_COMMIT();
        if (++sidx == NSTAGE) sidx = 0;
        if (++pidx == NSTAGE) pidx = 0;
    }

    // epilogue: register-resident --------------------------------------------
    #pragma unroll
    for (int mt = 0; mt < 2; ++mt) {
        const int mrow = m0 + wm * 32 + mt * 16 + (lane >> 2);
        #pragma unroll
        for (int nt = 0; nt < 2; ++nt) {
            const int nl = wn * 16 + nt * 8 + (lane & 3) * 2;
            const float bi0 = bias[nl],       bi1 = bias[nl + 1];
            const float bf0 = bias[64 + nl],  bf1 = bias[64 + nl + 1];
            const float bg0 = bias[128 + nl], bg1 = bias[128 + nl + 1];
            #pragma unroll
            for (int rh = 0; rh < 2; ++rh) {
                const long idx = (long)(mrow + rh * 8) * HID + n0 + nl;
                const float2 cv = *(const float2*)(c + idx);
                float2 ov;
                ov.x = lstm_elem(acc[0][mt][nt][rh * 2],
                                 acc[1][mt][nt][rh * 2],
                                 acc[2][mt][nt][rh * 2], bi0, bf0, bg0, cv.x);
                ov.y = lstm_elem(acc[0][mt][nt][rh * 2 + 1],
                                 acc[1][mt][nt][rh * 2 + 1],
                                 acc[2][mt][nt][rh * 2 + 1], bi1, bf1, bg1, cv.y);
                *(float2*)(out + idx) = ov;
            }
        }
    }
}

extern "C" void kernel_launch(void* const* d_in, const int* in_sizes, int n_in,
                              void* d_out, int out_size) {
    const float* x   = (const float*)d_in[0];
    const float* h   = (const float*)d_in[1];
    const float* c   = (const float*)d_in[2];
    const float* Wii = (const float*)d_in[3];
    const float* bii = (const float*)d_in[4];
    const float* Whi = (const float*)d_in[5];
    const float* bhi = (const float*)d_in[6];
    const float* Wif = (const float*)d_in[7];
    const float* bif = (const float*)d_in[8];
    const float* Whf = (const float*)d_in[9];
    const float* bhf = (const float*)d_in[10];
    const float* Wig = (const float*)d_in[11];
    const float* big = (const float*)d_in[12];
    const float* Whg = (const float*)d_in[13];
    const float* bhg = (const float*)d_in[14];
    float* out = (float*)d_out;

    cudaFuncSetAttribute(lstm_mma_kernel,
                         cudaFuncAttributeMaxDynamicSharedMemorySize, SMEM_BYTES);

    prep_kernel<<<(int)PREP_BLOCKS, PREP_THR>>>(x, h, Wii, Whi, Wif, Whf, Wig, Whg);

    dim3 grid((BATCH / BM) * (HID / BN_G));   // 4096
    lstm_mma_kernel<<<grid, NTHR, SMEM_BYTES>>>(
        c, bii, bhi, bif, bhf, big, bhg, out);
}